// round 8
// baseline (speedup 1.0000x reference)
#include <cuda_runtime.h>
#include <cuda_fp16.h>
#include <cstdint>
#include <math.h>

// ---------------------------------------------------------------------------
// Problem constants
// ---------------------------------------------------------------------------
#define H     128        // MEM_DIM
#define MSG   256        // MSG_DIM
#define BM    64         // rows per CTA (B=200000 = 3125*64)
#define BKH   32         // K halves per chunk
#define NCH   12         // 8 chunks X (K=256) + 4 chunks H (K=128)
#define NTHREADS 512
#define RSTR  40         // smem row stride in halves (80B, conflict-free ldmatrix)

// smem half-index offsets
#define SA0   0                    // 64  x 40
#define SA1   2560
#define SB0   5120                 // 3 stages of 384 x 40
#define BSTG  15360
#define NODES_BYTE  102400         // 64 ints
#define BRZ_BYTE    102656         // 256 f32
#define BIN_BYTE    103680         // 128 f32
#define BHN_BYTE    104192         // 128 f32
#define SMEM_BYTES  104704

#define FLAG_CAP (1 << 20)

// fp16 weight scratch + updated-row flags
__device__ half          g_Wih_h[384 * MSG];
__device__ half          g_Whh_h[384 * H];
__device__ unsigned char g_flag[FLAG_CAP];

__device__ __forceinline__ void ldsm_x4(uint32_t* r, uint32_t addr) {
    asm volatile("ldmatrix.sync.aligned.m8n8.x4.shared.b16 {%0,%1,%2,%3}, [%4];"
                 : "=r"(r[0]), "=r"(r[1]), "=r"(r[2]), "=r"(r[3]) : "r"(addr));
}
__device__ __forceinline__ void mma_f16(float* d, const uint32_t* a,
                                        uint32_t b0, uint32_t b1) {
    asm volatile(
        "mma.sync.aligned.m16n8k16.row.col.f32.f16.f16.f32 "
        "{%0,%1,%2,%3}, {%4,%5,%6,%7}, {%8,%9}, {%0,%1,%2,%3};"
        : "+f"(d[0]), "+f"(d[1]), "+f"(d[2]), "+f"(d[3])
        : "r"(a[0]), "r"(a[1]), "r"(a[2]), "r"(a[3]), "r"(b0), "r"(b1));
}
__device__ __forceinline__ uint32_t pack_h2(float x, float y) {
    half2 h = __float22half2_rn(make_float2(x, y));
    return *(uint32_t*)&h;
}
__device__ __forceinline__ void cp16(uint32_t smem_addr, const void* gptr) {
    asm volatile("cp.async.ca.shared.global [%0], [%1], 16;"
                 :: "r"(smem_addr), "l"(gptr) : "memory");
}
#define CP_COMMIT() asm volatile("cp.async.commit_group;" ::: "memory")
#define CP_WAIT1()  asm volatile("cp.async.wait_group 1;" ::: "memory")
#define CP_WAIT0()  asm volatile("cp.async.wait_group 0;" ::: "memory")

// ---------------------------------------------------------------------------
// Prep 1: zero flags + convert weights to fp16
// ---------------------------------------------------------------------------
__global__ void prep_kernel(const float* __restrict__ W_ih,
                            const float* __restrict__ W_hh, int n_nodes) {
    int i = blockIdx.x * blockDim.x + threadIdx.x;
    int stride = gridDim.x * blockDim.x;
    for (int j = i; j < n_nodes; j += stride) g_flag[j] = 0;
    for (int j = i; j < 384 * MSG + 384 * H; j += stride) {
        if (j < 384 * MSG) g_Wih_h[j] = __float2half_rn(W_ih[j]);
        else               g_Whh_h[j - 384 * MSG] = __float2half_rn(W_hh[j - 384 * MSG]);
    }
}
// Prep 2: mark updated rows
__global__ void flag_kernel(const int* __restrict__ node_ids, int B) {
    int i = blockIdx.x * blockDim.x + threadIdx.x;
    if (i < B) g_flag[node_ids[i]] = 1;
}

// ---------------------------------------------------------------------------
// Fused: GRU update (fp16 mma) + scatter + selective clone of the slice
// ---------------------------------------------------------------------------
__global__ __launch_bounds__(NTHREADS, 1)
void gru_fused_kernel(const float* __restrict__ memory,
                      const float* __restrict__ last_update,
                      const int*   __restrict__ node_ids,
                      const float* __restrict__ X,
                      const float* __restrict__ ts,
                      const float* __restrict__ b_ih,
                      const float* __restrict__ b_hh,
                      float* __restrict__ out_mem,
                      float* __restrict__ out_lu,
                      int B, int n_nodes, int rows_per_cta)
{
    extern __shared__ char smc[];
    half*  smh     = (half*)smc;
    int*   s_nodes = (int*)  (smc + NODES_BYTE);
    float* s_brz   = (float*)(smc + BRZ_BYTE);
    float* s_bin   = (float*)(smc + BIN_BYTE);
    float* s_bhn   = (float*)(smc + BHN_BYTE);
    const uint32_t sh_base = (uint32_t)__cvta_generic_to_shared(smc);

    const int tid  = threadIdx.x;
    const int lane = tid & 31;
    const int wid  = tid >> 5;
    const int wm   = wid >> 3;          // 0..1 : 32-row slab
    const int wn   = wid & 7;           // 0..7 : 16-col group per gate
    const int gid  = lane >> 2;
    const int tig  = lane & 3;
    const int row0 = blockIdx.x * BM;

    if (tid < BM) {
        int r = row0 + tid;
        s_nodes[tid] = node_ids[r < B ? r : (B - 1)];
    }
    if (tid < 256) s_brz[tid] = b_ih[tid] + b_hh[tid];
    else if (tid < 384) s_bin[tid - 256] = b_ih[tid];
    else { int j = tid - 384; s_bhn[j] = b_hh[256 + j]; }
    __syncthreads();

    // ---- B fill via cp.async: 1536 x 16B, 3 per thread ----
    const int b_r = tid >> 2, b_q = tid & 3;
    auto fill_B = [&](int stage, int c) {
        const uint32_t dst0 = sh_base + (uint32_t)(SB0 + stage * BSTG) * 2u;
        if (c < 8) {
            const half* src = g_Wih_h + c * BKH;
            #pragma unroll
            for (int i = 0; i < 3; i++) {
                int r = b_r + i * 128;
                cp16(dst0 + (uint32_t)(r * RSTR + b_q * 8) * 2u,
                     src + (long)r * MSG + b_q * 8);
            }
        } else {
            const half* src = g_Whh_h + (c - 8) * BKH;
            #pragma unroll
            for (int i = 0; i < 3; i++) {
                int r = b_r + i * 128;
                cp16(dst0 + (uint32_t)(r * RSTR + b_q * 8) * 2u,
                     src + (long)r * H + b_q * 8);
            }
        }
    };

    // ---- A fill: 1 float4/thread, register double-buffer ----
    const int a_r = tid >> 3, a_q = tid & 7;
    auto load_A = [&](int c) -> float4 {
        if (c < 8) {
            int gr = row0 + a_r; if (gr >= B) gr = B - 1;
            return *(const float4*)(X + (long)gr * MSG + c * BKH + a_q * 4);
        } else {
            int node = s_nodes[a_r];
            return *(const float4*)(memory + (long)node * H + (c - 8) * BKH + a_q * 4);
        }
    };
    auto store_A = [&](int s, float4 v) {
        half* sA = smh + (s ? SA1 : SA0);
        *(uint2*)(sA + a_r * RSTR + a_q * 4) =
            make_uint2(pack_h2(v.x, v.y), pack_h2(v.z, v.w));
    };

    // accumulators: [m-tile][0,1=r 2,3=z 4,5=i_n 6,7=h_n][frag]
    float acc[2][8][4];
    #pragma unroll
    for (int t = 0; t < 2; t++)
        #pragma unroll
        for (int g = 0; g < 8; g++)
            #pragma unroll
            for (int j = 0; j < 4; j++) acc[t][g][j] = 0.f;

    // ---- prologue: commit chunk0, chunk1 ----
    fill_B(0, 0); CP_COMMIT();
    fill_B(1, 1); CP_COMMIT();
    float4 pa = load_A(0);
    store_A(0, pa);
    pa = load_A(1);

    const int lr = lane & 15;
    const int lk = (lane >> 4) * 8;

    for (int c = 0; c < NCH; c++) {
        // retire chunk c (groups complete in commit order)
        if (c + 1 < NCH) CP_WAIT1(); else CP_WAIT0();
        __syncthreads();   // all warps done reading stage (c+2)%3 (= chunk c-1)

        // fill next stage strictly AFTER the barrier -> no overwrite race
        if (c + 2 < NCH) { fill_B((c + 2) % 3, c + 2); CP_COMMIT(); }
        if (c + 1 < NCH) {
            store_A((c + 1) & 1, pa);
            if (c + 2 < NCH) pa = load_A(c + 2);
        }

        const uint32_t baseA = sh_base + (uint32_t)((c & 1) ? SA1 : SA0) * 2u;
        const uint32_t baseB = sh_base + (uint32_t)(SB0 + (c % 3) * BSTG) * 2u;
        const int nb = (c < 8) ? 4 : 6;

        #pragma unroll
        for (int kk = 0; kk < 2; kk++) {
            const uint32_t kof = (uint32_t)(kk * 16 + lk) * 2u;
            uint32_t a[2][4], br[4], bz[4], bn[4];
            ldsm_x4(a[0], baseA + (uint32_t)(wm * 32 +  0 + lr) * (RSTR * 2u) + kof);
            ldsm_x4(a[1], baseA + (uint32_t)(wm * 32 + 16 + lr) * (RSTR * 2u) + kof);
            ldsm_x4(br,   baseB + (uint32_t)(      wn * 16 + lr) * (RSTR * 2u) + kof);
            ldsm_x4(bz,   baseB + (uint32_t)(128 + wn * 16 + lr) * (RSTR * 2u) + kof);
            ldsm_x4(bn,   baseB + (uint32_t)(256 + wn * 16 + lr) * (RSTR * 2u) + kof);
            #pragma unroll
            for (int t = 0; t < 2; t++) {
                mma_f16(acc[t][0],      a[t], br[0], br[2]);
                mma_f16(acc[t][1],      a[t], br[1], br[3]);
                mma_f16(acc[t][2],      a[t], bz[0], bz[2]);
                mma_f16(acc[t][3],      a[t], bz[1], bz[3]);
                mma_f16(acc[t][nb],     a[t], bn[0], bn[2]);
                mma_f16(acc[t][nb + 1], a[t], bn[1], bn[3]);
            }
        }
    }

    // ---- register-local epilogue: gates + scatter ----
    #pragma unroll
    for (int t = 0; t < 2; t++) {
        #pragma unroll
        for (int s = 0; s < 2; s++) {
            const int r_local = wm * 32 + t * 16 + gid + s * 8;
            const int grow = row0 + r_local;
            if (grow < B) {
                const int node = s_nodes[r_local];
                #pragma unroll
                for (int nt = 0; nt < 2; nt++) {
                    const int c0 = wn * 16 + nt * 8 + tig * 2;
                    float2 hv = *(const float2*)(memory + (long)node * H + c0);
                    float hh[2] = {hv.x, hv.y};
                    float o[2];
                    #pragma unroll
                    for (int j = 0; j < 2; j++) {
                        const int fi = s * 2 + j;
                        float rg = 1.0f / (1.0f + __expf(-(acc[t][nt][fi]     + s_brz[c0 + j])));
                        float zg = 1.0f / (1.0f + __expf(-(acc[t][2 + nt][fi] + s_brz[128 + c0 + j])));
                        float ng = tanhf(acc[t][4 + nt][fi] + s_bin[c0 + j]
                                         + rg * (acc[t][6 + nt][fi] + s_bhn[c0 + j]));
                        o[j] = (1.0f - zg) * ng + zg * hh[j];
                    }
                    *(float2*)(out_mem + (long)node * H + c0) = make_float2(o[0], o[1]);
                }
            }
        }
    }
    if (tid < BM) {
        int r = row0 + tid;
        if (r < B) out_lu[s_nodes[tid]] = ts[r];
    }

    // ---- selective clone of this CTA's slice (flag==0 rows only) ----
    const long slice0 = (long)blockIdx.x * rows_per_cta;
    for (int ro = wid; ro < rows_per_cta; ro += 16) {        // warp per row
        long row = slice0 + ro;
        if (row < n_nodes && !g_flag[row]) {
            const float4* src = (const float4*)(memory + row * H);
            float4*       dst = (float4*)(out_mem + row * H);
            dst[lane] = src[lane];                            // 32 x 16B = 512B
        }
    }
    for (int i = tid; i < rows_per_cta; i += NTHREADS) {
        long row = slice0 + i;
        if (row < n_nodes && !g_flag[row]) out_lu[row] = last_update[row];
    }
}

// ---------------------------------------------------------------------------
// Launch. Inputs (metadata order):
//   0 memory [N,128] | 1 last_update [N] | 2 unique_node_ids [B] i32
//   3 unique_messages [B,256] | 4 timestamps [B]
//   5 W_ih [384,256] | 6 W_hh [384,128] | 7 b_ih [384] | 8 b_hh [384]
// Output: concat(updated_memory [N*128], updated_last_update [N]) f32
// ---------------------------------------------------------------------------
extern "C" void kernel_launch(void* const* d_in, const int* in_sizes, int n_in,
                              void* d_out, int out_size) {
    const float* memory      = (const float*)d_in[0];
    const float* last_update = (const float*)d_in[1];
    const int*   node_ids    = (const int*)  d_in[2];
    const float* X           = (const float*)d_in[3];
    const float* ts          = (const float*)d_in[4];
    const float* W_ih        = (const float*)d_in[5];
    const float* W_hh        = (const float*)d_in[6];
    const float* b_ih        = (const float*)d_in[7];
    const float* b_hh        = (const float*)d_in[8];

    const int n_nodes = in_sizes[1];
    const int B       = in_sizes[2];

    float* out_mem = (float*)d_out;
    float* out_lu  = out_mem + (long)n_nodes * H;

    // prep: zero flags + fp16 weights, then mark updated rows
    prep_kernel<<<1024, 512>>>(W_ih, W_hh, n_nodes);
    flag_kernel<<<(B + 511) / 512, 512>>>(node_ids, B);

    // fused GRU + selective clone
    int blocks = (B + BM - 1) / BM;
    int rows_per_cta = (n_nodes + blocks - 1) / blocks;
    cudaFuncSetAttribute(gru_fused_kernel,
                         cudaFuncAttributeMaxDynamicSharedMemorySize, SMEM_BYTES);
    gru_fused_kernel<<<blocks, NTHREADS, SMEM_BYTES>>>(
        memory, last_update, node_ids, X, ts, b_ih, b_hh,
        out_mem, out_lu, B, n_nodes, rows_per_cta);
}